// round 1
// baseline (speedup 1.0000x reference)
#include <cuda_runtime.h>
#include <cuda_bf16.h>

// Problem constants
#define BSZ 4
#define LEN 2048
#define NH  12
#define HD  64
#define RR  16
#define HID 768
#define MM  (BSZ*LEN)   // 8192 rows
#define NN  (NH*HD)     // 768 cols
#define KK  HID         // 768 reduction

// Scratch (no allocation allowed -> __device__ globals)
__device__ float g_V1[(size_t)MM * NN];     // relu(hidden @ V1_w + b)  25.2 MB
__device__ float g_dot[(size_t)MM * NH];    // dot(relu(K1), ReadingHead)
__device__ int   g_fm[(size_t)MM * NH * RR];
__device__ int   g_bm[(size_t)MM * NH * RR];

// ---------------------------------------------------------------------------
// Fused GEMM: C = relu(A @ W + bias)
//   DOT=false: store C into g_V1
//   DOT=true : reduce C * RH per head into g_dot (K1 never materialized)
// Tiles: BM=128, BN=64, BK=16, 256 threads, 8x4 per-thread microtile.
// ---------------------------------------------------------------------------
template<bool DOT>
__global__ __launch_bounds__(256) void gemm_relu_kernel(
    const float* __restrict__ A,
    const float* __restrict__ W,
    const float* __restrict__ bias,
    const float* __restrict__ RH)
{
    __shared__ float As[16][128];
    __shared__ float Bs[16][64];
    __shared__ float sdot[128];

    const int tid = threadIdx.x;
    const int tx = tid & 15;       // 0..15 -> col group
    const int ty = tid >> 4;       // 0..15 -> row group
    const int m0 = blockIdx.y * 128;
    const int n0 = blockIdx.x * 64;

    float acc[8][4];
#pragma unroll
    for (int i = 0; i < 8; i++)
#pragma unroll
        for (int j = 0; j < 4; j++) acc[i][j] = 0.f;

    for (int kt = 0; kt < KK; kt += 16) {
        // Load A tile 128x16 (512 float4), transposed store As[k][m]
#pragma unroll
        for (int s = 0; s < 2; s++) {
            int p  = tid + 256 * s;       // 0..511
            int mm = p >> 2;              // 0..127
            int k4 = (p & 3) << 2;        // 0,4,8,12
            float4 v = *(const float4*)(A + (size_t)(m0 + mm) * KK + kt + k4);
            As[k4 + 0][mm] = v.x;
            As[k4 + 1][mm] = v.y;
            As[k4 + 2][mm] = v.z;
            As[k4 + 3][mm] = v.w;
        }
        // Load W tile 16x64 (256 float4)
        {
            int kki = tid >> 4;           // 0..15
            int n4  = (tid & 15) << 2;    // 0..60
            float4 v = *(const float4*)(W + (size_t)(kt + kki) * NN + n0 + n4);
            *(float4*)&Bs[kki][n4] = v;
        }
        __syncthreads();

#pragma unroll
        for (int kk = 0; kk < 16; kk++) {
            float a[8], b[4];
            *(float4*)&a[0] = *(const float4*)&As[kk][ty * 8];
            *(float4*)&a[4] = *(const float4*)&As[kk][ty * 8 + 4];
            *(float4*)&b[0] = *(const float4*)&Bs[kk][tx * 4];
#pragma unroll
            for (int i = 0; i < 8; i++)
#pragma unroll
                for (int j = 0; j < 4; j++)
                    acc[i][j] += a[i] * b[j];
        }
        __syncthreads();
    }

    // bias + relu
    float bsv[4];
#pragma unroll
    for (int j = 0; j < 4; j++) bsv[j] = bias[n0 + tx * 4 + j];

    if (!DOT) {
#pragma unroll
        for (int i = 0; i < 8; i++) {
            float4 v;
            v.x = fmaxf(acc[i][0] + bsv[0], 0.f);
            v.y = fmaxf(acc[i][1] + bsv[1], 0.f);
            v.z = fmaxf(acc[i][2] + bsv[2], 0.f);
            v.w = fmaxf(acc[i][3] + bsv[3], 0.f);
            *(float4*)&g_V1[(size_t)(m0 + ty * 8 + i) * NN + n0 + tx * 4] = v;
        }
    } else {
        // head h = blockIdx.x (BN==HD==64). Reduce relu(C)*RH over the 64 cols.
        if (tid < 128) sdot[tid] = 0.f;
        __syncthreads();
        float rh[4];
#pragma unroll
        for (int j = 0; j < 4; j++) rh[j] = RH[n0 + tx * 4 + j];
#pragma unroll
        for (int i = 0; i < 8; i++) {
            float p = 0.f;
#pragma unroll
            for (int j = 0; j < 4; j++)
                p += fmaxf(acc[i][j] + bsv[j], 0.f) * rh[j];
            atomicAdd(&sdot[ty * 8 + i], p);
        }
        __syncthreads();
        if (tid < 128)
            g_dot[(size_t)(m0 + tid) * NH + blockIdx.x] = sdot[tid];
    }
}

// ---------------------------------------------------------------------------
// Scan kernel: per (b,h), prefix-count of mask (positions 1..L-1 only!),
// event list, then fm/bm index tables. One block of 256 threads per (b,h).
// fm[l,r] = r-th most recent valid idx <= l (0 if none / l==0)
// bm[l,r] = r-th nearest valid idx >= l   (0 if none / l==0)
// ---------------------------------------------------------------------------
__global__ __launch_bounds__(256) void scan_kernel()
{
    const int bh = blockIdx.x;
    const int b = bh / NH, h = bh % NH;

    __shared__ int s_cnt[LEN];
    __shared__ int s_e[LEN];
    __shared__ int s_wsum[8];

    const int tid = threadIdx.x;
    const int base = tid * 8;

    int c[8];
    unsigned mbits = 0;
    int run = 0;
#pragma unroll
    for (int q = 0; q < 8; q++) {
        int l = base + q;
        bool m = (l >= 1) &&
                 (g_dot[(size_t)(b * LEN + l) * NH + h] > 0.5f);
        if (m) { mbits |= 1u << q; run++; }
        c[q] = run;
    }

    // block-wide exclusive scan of per-thread totals
    const int lane = tid & 31, wid = tid >> 5;
    int v = run;
#pragma unroll
    for (int o = 1; o < 32; o <<= 1) {
        int nv = __shfl_up_sync(0xffffffffu, v, o);
        if (lane >= o) v += nv;
    }
    if (lane == 31) s_wsum[wid] = v;
    __syncthreads();
    int wpre = 0;
    for (int w = 0; w < wid; w++) wpre += s_wsum[w];
    const int excl = wpre + v - run;   // exclusive prefix at this thread's chunk

#pragma unroll
    for (int q = 0; q < 8; q++) {
        s_cnt[base + q] = excl + c[q];
        if (mbits & (1u << q)) s_e[excl + c[q] - 1] = base + q;
    }
    __syncthreads();

    const int E = s_cnt[LEN - 1];

    for (int l = tid; l < LEN; l += 256) {
        int cl = s_cnt[l];
        int cp = (l > 0) ? s_cnt[l - 1] : 0;
        int fo[RR], bo[RR];
#pragma unroll
        for (int r = 0; r < RR; r++) {
            fo[r] = (cl > r) ? s_e[cl - 1 - r] : 0;
            bo[r] = (l > 0 && cp + r < E) ? s_e[cp + r] : 0;
        }
        size_t off = ((size_t)(b * LEN + l) * NH + h) * RR;
#pragma unroll
        for (int r4 = 0; r4 < RR; r4 += 4) {
            *(int4*)&g_fm[off + r4] = make_int4(fo[r4], fo[r4+1], fo[r4+2], fo[r4+3]);
            *(int4*)&g_bm[off + r4] = make_int4(bo[r4], bo[r4+1], bo[r4+2], bo[r4+3]);
        }
    }
}

// ---------------------------------------------------------------------------
// Gather + weighted sum:
// ctx[b,l,h,d] = sum_r wF[h,r]*V1[b,fm,h,d] + wB[h,r]*V1[b,bm,h,d]
// 64 threads per (b,l,h) tuple, 4 tuples per 256-thread block.
// V1 (25MB) fits in L2; gathers are temporally local.
// ---------------------------------------------------------------------------
__global__ __launch_bounds__(256) void gather_kernel(
    const float* __restrict__ w, float* __restrict__ out)
{
    const int t = blockIdx.x * 4 + (threadIdx.x >> 6);  // tuple = row*NH + h
    const int d = threadIdx.x & 63;
    const int h = t % NH;
    const int row = t / NH;          // b*LEN + l
    const int b = row / LEN;

    const int* fp = g_fm + (size_t)t * RR;
    const int* bp = g_bm + (size_t)t * RR;
    const float* wf = w + h * 2 * RR;

    const size_t vbase = (size_t)b * LEN * NN + h * HD + d;

    float acc = 0.f;
#pragma unroll
    for (int r = 0; r < RR; r++) {
        int i1 = __ldg(fp + r);
        int i2 = __ldg(bp + r);
        acc += wf[r]      * __ldg(&g_V1[vbase + (size_t)i1 * NN]);
        acc += wf[RR + r] * __ldg(&g_V1[vbase + (size_t)i2 * NN]);
    }
    out[(size_t)t * HD + d] = acc;
}

// ---------------------------------------------------------------------------
extern "C" void kernel_launch(void* const* d_in, const int* in_sizes, int n_in,
                              void* d_out, int out_size)
{
    const float* hidden = (const float*)d_in[0];
    const float* K1w    = (const float*)d_in[1];
    const float* K1b    = (const float*)d_in[2];
    const float* V1w    = (const float*)d_in[3];
    const float* V1b    = (const float*)d_in[4];
    const float* RH     = (const float*)d_in[5];
    const float* bw     = (const float*)d_in[6];
    float* out = (float*)d_out;

    dim3 gg(NN / 64, MM / 128);  // (12, 64)
    gemm_relu_kernel<false><<<gg, 256>>>(hidden, V1w, V1b, nullptr);
    gemm_relu_kernel<true ><<<gg, 256>>>(hidden, K1w, K1b, RH);
    scan_kernel<<<BSZ * NH, 256>>>();
    gather_kernel<<<(MM * NH) / 4, 256>>>(bw, out);
}

// round 3
// speedup vs baseline: 3.5069x; 3.5069x over previous
#include <cuda_runtime.h>
#include <cuda_bf16.h>
#include <cstdint>

// Problem constants
#define BSZ 4
#define LEN 2048
#define NH  12
#define HD  64
#define RR  16
#define HID 768
#define MM  (BSZ*LEN)   // 8192
#define NN  (NH*HD)     // 768
#define KK  HID         // 768

// ---------------------------------------------------------------------------
// Scratch (__device__ globals; allocation is forbidden)
// ---------------------------------------------------------------------------
__device__ __nv_bfloat16 g_Ahi[(size_t)MM * KK];
__device__ __nv_bfloat16 g_Alo[(size_t)MM * KK];
__device__ __nv_bfloat16 g_WhiK[(size_t)NN * KK];   // transposed: [n][k]
__device__ __nv_bfloat16 g_WloK[(size_t)NN * KK];
__device__ __nv_bfloat16 g_WhiV[(size_t)NN * KK];
__device__ __nv_bfloat16 g_WloV[(size_t)NN * KK];
__device__ float g_V1[(size_t)MM * NN];
__device__ float g_dot[(size_t)MM * NH];
__device__ int   g_fm[(size_t)MM * NH * RR];
__device__ int   g_bm[(size_t)MM * NH * RR];

// ---------------------------------------------------------------------------
// Baseline-PTX helpers (sm_80+: mma.sync / ldmatrix / cp.async — NO tcgen05!)
// ---------------------------------------------------------------------------
__device__ __forceinline__ uint32_t smem_u32(const void* p) {
    uint32_t a;
    asm("{ .reg .u64 t; cvta.to.shared.u64 t, %1; cvt.u32.u64 %0, t; }"
        : "=r"(a) : "l"(p));
    return a;
}

__device__ __forceinline__ void cp16(uint32_t dst, const void* src) {
    asm volatile("cp.async.cg.shared.global [%0], [%1], 16;"
                 :: "r"(dst), "l"(src));
}
__device__ __forceinline__ void cp_commit() {
    asm volatile("cp.async.commit_group;");
}
template<int N> __device__ __forceinline__ void cp_wait() {
    asm volatile("cp.async.wait_group %0;" :: "n"(N));
}

__device__ __forceinline__ void ldsm4(uint32_t* r, uint32_t addr) {
    asm volatile("ldmatrix.sync.aligned.m8n8.x4.shared.b16 {%0,%1,%2,%3}, [%4];"
                 : "=r"(r[0]), "=r"(r[1]), "=r"(r[2]), "=r"(r[3]) : "r"(addr));
}

__device__ __forceinline__ void mma16816(float* c, const uint32_t* a,
                                         uint32_t b0, uint32_t b1) {
    asm volatile(
        "mma.sync.aligned.m16n8k16.row.col.f32.bf16.bf16.f32 "
        "{%0,%1,%2,%3}, {%4,%5,%6,%7}, {%8,%9}, {%0,%1,%2,%3};"
        : "+f"(c[0]), "+f"(c[1]), "+f"(c[2]), "+f"(c[3])
        : "r"(a[0]), "r"(a[1]), "r"(a[2]), "r"(a[3]), "r"(b0), "r"(b1));
}

// ---------------------------------------------------------------------------
// Split-conversion kernels (fp32 -> bf16 hi + bf16 lo)
// ---------------------------------------------------------------------------
__device__ __forceinline__ uint32_t pack_bf2(__nv_bfloat16 a, __nv_bfloat16 b) {
    return ((uint32_t)__bfloat16_as_ushort(b) << 16) | (uint32_t)__bfloat16_as_ushort(a);
}

__global__ __launch_bounds__(256) void convA_kernel(const float* __restrict__ A) {
    size_t i = ((size_t)blockIdx.x * 256 + threadIdx.x) * 4;
    float4 v = *(const float4*)(A + i);
    __nv_bfloat16 h0 = __float2bfloat16(v.x), h1 = __float2bfloat16(v.y);
    __nv_bfloat16 h2 = __float2bfloat16(v.z), h3 = __float2bfloat16(v.w);
    __nv_bfloat16 l0 = __float2bfloat16(v.x - __bfloat162float(h0));
    __nv_bfloat16 l1 = __float2bfloat16(v.y - __bfloat162float(h1));
    __nv_bfloat16 l2 = __float2bfloat16(v.z - __bfloat162float(h2));
    __nv_bfloat16 l3 = __float2bfloat16(v.w - __bfloat162float(h3));
    uint2 ph = make_uint2(pack_bf2(h0, h1), pack_bf2(h2, h3));
    uint2 pl = make_uint2(pack_bf2(l0, l1), pack_bf2(l2, l3));
    *(uint2*)((char*)g_Ahi + i * 2) = ph;
    *(uint2*)((char*)g_Alo + i * 2) = pl;
}

// Transpose W [k][n] -> [n][k], split hi/lo. WHICH==0 -> K weights, 1 -> V.
template<int WHICH>
__global__ void convW_kernel(const float* __restrict__ W) {
    __shared__ float t[32][33];
    int bx = blockIdx.x * 32;  // n tile
    int by = blockIdx.y * 32;  // k tile
    int tx = threadIdx.x, ty = threadIdx.y;
#pragma unroll
    for (int j = 0; j < 4; j++) {
        int r = ty + j * 8;
        t[r][tx] = W[(size_t)(by + r) * NN + bx + tx];
    }
    __syncthreads();
#pragma unroll
    for (int j = 0; j < 4; j++) {
        int r = ty + j * 8;
        float x = t[tx][r];  // = W[by+tx][bx+r]
        __nv_bfloat16 h = __float2bfloat16(x);
        __nv_bfloat16 l = __float2bfloat16(x - __bfloat162float(h));
        size_t o = (size_t)(bx + r) * KK + by + tx;
        if (WHICH == 0) { g_WhiK[o] = h; g_WloK[o] = l; }
        else            { g_WhiV[o] = h; g_WloV[o] = l; }
    }
}

// ---------------------------------------------------------------------------
// mma.sync GEMM, bf16x3: C = relu(A @ Wt + bias); Wt stored [n][k].
// BM=128, BN=64 (== HD, so blockIdx.x == head), BK=32, 8 warps (4x2),
// each warp computes 32x32. Double-buffered cp.async pipeline.
//   DOT=false: C -> g_V1
//   DOT=true : per-row dot(relu(C), RH[head]) -> g_dot
// SMEM per stage: Ahi[128][40bf16] Alo BhI[64][40] Blo (80B padded rows).
// ---------------------------------------------------------------------------
#define A_STRIDE 80
#define OFF_AH 0
#define OFF_AL 10240
#define OFF_BH 20480
#define OFF_BL 25600
#define STAGE  30720
#define SM_TOTAL (2 * STAGE)
#define NCHUNK (KK / 32)

template<bool DOT>
__global__ __launch_bounds__(256) void mma_gemm_kernel(
    const float* __restrict__ bias, const float* __restrict__ RH)
{
    extern __shared__ char smem[];
    __shared__ float sdot[128];
    const uint32_t sb = smem_u32(smem);

    const __nv_bfloat16* __restrict__ Bh = DOT ? g_WhiK : g_WhiV;
    const __nv_bfloat16* __restrict__ Bl = DOT ? g_WloK : g_WloV;

    const int tid = threadIdx.x;
    const int lane = tid & 31;
    const int wid = tid >> 5;
    const int mw = wid & 3;   // m warp row (32 rows)
    const int nw = wid >> 2;  // n warp col (32 cols)

    const int head = blockIdx.x;       // BN == HD == 64
    const int n0 = head * 64;
    const int m0 = blockIdx.y * 128;

    // ldmatrix per-lane invariant offsets
    const uint32_t a_lo = (uint32_t)((mw * 32 + (lane & 15)) * A_STRIDE
                                     + ((lane >> 4) * 8) * 2);
    const uint32_t b_lo = (uint32_t)((nw * 32 + (lane & 7) + ((lane >> 4) << 3)) * A_STRIDE
                                     + (((lane >> 3) & 1) * 8) * 2);

    // cp.async per-thread assignments
    const int a_row0 = tid >> 2;         // 0..63  (plus +64 second pass)
    const int a_cc = tid & 3;
    const int b_row = tid >> 2;          // 0..63
    const int b_cc = tid & 3;

    float acc[2][4][4];
#pragma unroll
    for (int i = 0; i < 2; i++)
#pragma unroll
        for (int j = 0; j < 4; j++)
#pragma unroll
            for (int q = 0; q < 4; q++) acc[i][j][q] = 0.f;

    // ---- pipeline: load chunk into stage, compute previous ----
    auto load_chunk = [&](int c, int st) {
        const int kt = c * 32;
        const uint32_t stb = sb + st * STAGE;
#pragma unroll
        for (int i = 0; i < 2; i++) {
            int row = a_row0 + i * 64;
            uint32_t so = row * A_STRIDE + a_cc * 16;
            size_t go = (size_t)(m0 + row) * KK + kt + a_cc * 8;
            cp16(stb + OFF_AH + so, g_Ahi + go);
            cp16(stb + OFF_AL + so, g_Alo + go);
        }
        {
            uint32_t so = b_row * A_STRIDE + b_cc * 16;
            size_t go = (size_t)(n0 + b_row) * KK + kt + b_cc * 8;
            cp16(stb + OFF_BH + so, Bh + go);
            cp16(stb + OFF_BL + so, Bl + go);
        }
        cp_commit();
    };

    load_chunk(0, 0);

    for (int c = 0; c < NCHUNK; c++) {
        if (c + 1 < NCHUNK) {
            load_chunk(c + 1, (c + 1) & 1);
            cp_wait<1>();
        } else {
            cp_wait<0>();
        }
        __syncthreads();

        const uint32_t stb = sb + (c & 1) * STAGE;
#pragma unroll
        for (int ks = 0; ks < 2; ks++) {
            uint32_t ah[2][4], al[2][4], bh[2][4], bl[2][4];
#pragma unroll
            for (int mi = 0; mi < 2; mi++) {
                uint32_t ao = a_lo + ks * 32 + mi * (16 * A_STRIDE);
                ldsm4(ah[mi], stb + OFF_AH + ao);
                ldsm4(al[mi], stb + OFF_AL + ao);
            }
#pragma unroll
            for (int nt = 0; nt < 2; nt++) {
                uint32_t bo = b_lo + ks * 32 + nt * (16 * A_STRIDE);
                ldsm4(bh[nt], stb + OFF_BH + bo);
                ldsm4(bl[nt], stb + OFF_BL + bo);
            }
#pragma unroll
            for (int mi = 0; mi < 2; mi++)
#pragma unroll
                for (int nj = 0; nj < 4; nj++) {
                    const int nt = nj >> 1, rb = (nj & 1) * 2;
                    mma16816(acc[mi][nj], ah[mi], bh[nt][rb], bh[nt][rb + 1]);
                    mma16816(acc[mi][nj], ah[mi], bl[nt][rb], bl[nt][rb + 1]);
                    mma16816(acc[mi][nj], al[mi], bh[nt][rb], bh[nt][rb + 1]);
                }
        }
        __syncthreads();
    }

    // ---- epilogue ----
    const int rrow = lane >> 2;
    const int cq = (lane & 3) * 2;

    if (!DOT) {
#pragma unroll
        for (int mi = 0; mi < 2; mi++) {
            const int r0 = m0 + mw * 32 + mi * 16 + rrow;
#pragma unroll
            for (int nj = 0; nj < 4; nj++) {
                const int n = n0 + nw * 32 + nj * 8 + cq;
                const float b0v = bias[n], b1v = bias[n + 1];
                float2 v0, v1;
                v0.x = fmaxf(acc[mi][nj][0] + b0v, 0.f);
                v0.y = fmaxf(acc[mi][nj][1] + b1v, 0.f);
                v1.x = fmaxf(acc[mi][nj][2] + b0v, 0.f);
                v1.y = fmaxf(acc[mi][nj][3] + b1v, 0.f);
                *(float2*)&g_V1[(size_t)r0 * NN + n] = v0;
                *(float2*)&g_V1[(size_t)(r0 + 8) * NN + n] = v1;
            }
        }
    } else {
        if (tid < 128) sdot[tid] = 0.f;
        __syncthreads();
#pragma unroll
        for (int mi = 0; mi < 2; mi++) {
            float s0 = 0.f, s1 = 0.f;
#pragma unroll
            for (int nj = 0; nj < 4; nj++) {
                const int n = n0 + nw * 32 + nj * 8 + cq;
                const float b0v = bias[n], b1v = bias[n + 1];
                const float rh0 = RH[n], rh1 = RH[n + 1];
                s0 += fmaxf(acc[mi][nj][0] + b0v, 0.f) * rh0
                    + fmaxf(acc[mi][nj][1] + b1v, 0.f) * rh1;
                s1 += fmaxf(acc[mi][nj][2] + b0v, 0.f) * rh0
                    + fmaxf(acc[mi][nj][3] + b1v, 0.f) * rh1;
            }
            s0 += __shfl_xor_sync(0xffffffffu, s0, 1);
            s0 += __shfl_xor_sync(0xffffffffu, s0, 2);
            s1 += __shfl_xor_sync(0xffffffffu, s1, 1);
            s1 += __shfl_xor_sync(0xffffffffu, s1, 2);
            if ((lane & 3) == 0) {
                atomicAdd(&sdot[mw * 32 + mi * 16 + rrow], s0);
                atomicAdd(&sdot[mw * 32 + mi * 16 + rrow + 8], s1);
            }
        }
        __syncthreads();
        if (tid < 128)
            g_dot[(size_t)(m0 + tid) * NH + head] = sdot[tid];
    }
}

// ---------------------------------------------------------------------------
// Scan kernel (per (b,h)): prefix-count + event list -> fm/bm index tables
// ---------------------------------------------------------------------------
__global__ __launch_bounds__(256) void scan_kernel()
{
    const int bh = blockIdx.x;
    const int b = bh / NH, h = bh % NH;

    __shared__ int s_cnt[LEN];
    __shared__ int s_e[LEN];
    __shared__ int s_wsum[8];

    const int tid = threadIdx.x;
    const int base = tid * 8;

    int c[8];
    unsigned mbits = 0;
    int run = 0;
#pragma unroll
    for (int q = 0; q < 8; q++) {
        int l = base + q;
        bool m = (l >= 1) && (g_dot[(size_t)(b * LEN + l) * NH + h] > 0.5f);
        if (m) { mbits |= 1u << q; run++; }
        c[q] = run;
    }

    const int lane = tid & 31, wd = tid >> 5;
    int v = run;
#pragma unroll
    for (int o = 1; o < 32; o <<= 1) {
        int nv = __shfl_up_sync(0xffffffffu, v, o);
        if (lane >= o) v += nv;
    }
    if (lane == 31) s_wsum[wd] = v;
    __syncthreads();
    int wpre = 0;
    for (int w = 0; w < wd; w++) wpre += s_wsum[w];
    const int excl = wpre + v - run;

#pragma unroll
    for (int q = 0; q < 8; q++) {
        s_cnt[base + q] = excl + c[q];
        if (mbits & (1u << q)) s_e[excl + c[q] - 1] = base + q;
    }
    __syncthreads();

    const int E = s_cnt[LEN - 1];

    for (int l = tid; l < LEN; l += 256) {
        int cl = s_cnt[l];
        int cp = (l > 0) ? s_cnt[l - 1] : 0;
        int fo[RR], bo[RR];
#pragma unroll
        for (int r = 0; r < RR; r++) {
            fo[r] = (cl > r) ? s_e[cl - 1 - r] : 0;
            bo[r] = (l > 0 && cp + r < E) ? s_e[cp + r] : 0;
        }
        size_t off = ((size_t)(b * LEN + l) * NH + h) * RR;
#pragma unroll
        for (int r4 = 0; r4 < RR; r4 += 4) {
            *(int4*)&g_fm[off + r4] = make_int4(fo[r4], fo[r4+1], fo[r4+2], fo[r4+3]);
            *(int4*)&g_bm[off + r4] = make_int4(bo[r4], bo[r4+1], bo[r4+2], bo[r4+3]);
        }
    }
}

// ---------------------------------------------------------------------------
// Gather + weighted sum: 16 threads per (b,l,h) tuple, float4 gathers.
// ---------------------------------------------------------------------------
__global__ __launch_bounds__(256) void gather_kernel(
    const float* __restrict__ w, float* __restrict__ out)
{
    const int t = blockIdx.x * 16 + (threadIdx.x >> 4);  // row*NH + h
    const int d4 = (threadIdx.x & 15) * 4;
    const int h = t % NH;
    const int row = t / NH;
    const int b = row >> 11;

    const int* fp = g_fm + (size_t)t * RR;
    const int* bp = g_bm + (size_t)t * RR;
    const float* wf = w + h * 2 * RR;

    const float* vb = g_V1 + (size_t)b * LEN * NN + h * HD + d4;

    float ax = 0.f, ay = 0.f, az = 0.f, aw = 0.f;
#pragma unroll
    for (int r = 0; r < RR; r++) {
        int i1 = __ldg(fp + r);
        int i2 = __ldg(bp + r);
        float w1 = __ldg(wf + r);
        float w2 = __ldg(wf + RR + r);
        float4 v1 = *(const float4*)(vb + (size_t)i1 * NN);
        float4 v2 = *(const float4*)(vb + (size_t)i2 * NN);
        ax = fmaf(w1, v1.x, fmaf(w2, v2.x, ax));
        ay = fmaf(w1, v1.y, fmaf(w2, v2.y, ay));
        az = fmaf(w1, v1.z, fmaf(w2, v2.z, az));
        aw = fmaf(w1, v1.w, fmaf(w2, v2.w, aw));
    }
    *(float4*)(out + (size_t)t * HD + d4) = make_float4(ax, ay, az, aw);
}

// ---------------------------------------------------------------------------
extern "C" void kernel_launch(void* const* d_in, const int* in_sizes, int n_in,
                              void* d_out, int out_size)
{
    const float* hidden = (const float*)d_in[0];
    const float* K1w    = (const float*)d_in[1];
    const float* K1b    = (const float*)d_in[2];
    const float* V1w    = (const float*)d_in[3];
    const float* V1b    = (const float*)d_in[4];
    const float* RH     = (const float*)d_in[5];
    const float* bw     = (const float*)d_in[6];
    float* out = (float*)d_out;

    cudaFuncSetAttribute(mma_gemm_kernel<false>,
                         cudaFuncAttributeMaxDynamicSharedMemorySize, SM_TOTAL);
    cudaFuncSetAttribute(mma_gemm_kernel<true>,
                         cudaFuncAttributeMaxDynamicSharedMemorySize, SM_TOTAL);

    // 1) Split fp32 -> bf16 hi/lo (weights also transposed to [n][k])
    convA_kernel<<<(MM * KK) / 1024, 256>>>(hidden);
    {
        dim3 tg(NN / 32, KK / 32), tb(32, 8);
        convW_kernel<0><<<tg, tb>>>(K1w);
        convW_kernel<1><<<tg, tb>>>(V1w);
    }

    // 2) Tensor-core GEMMs (bf16x3 via mma.sync)
    {
        dim3 gg(NN / 64, MM / 128);  // (12, 64)
        mma_gemm_kernel<false><<<gg, 256, SM_TOTAL>>>(V1b, nullptr);
        mma_gemm_kernel<true ><<<gg, 256, SM_TOTAL>>>(K1b, RH);
    }

    // 3) Mask scan -> index tables
    scan_kernel<<<BSZ * NH, 256>>>();

    // 4) Gather + weighted sum
    gather_kernel<<<(MM * NH) / 16, 256>>>(bw, out);
}

// round 4
// speedup vs baseline: 3.5731x; 1.0189x over previous
#include <cuda_runtime.h>
#include <cuda_bf16.h>
#include <cstdint>

// Problem constants
#define BSZ 4
#define LEN 2048
#define NH  12
#define HD  64
#define RR  16
#define HID 768
#define MM  (BSZ*LEN)   // 8192
#define NN  (NH*HD)     // 768
#define KK  HID         // 768

// ---------------------------------------------------------------------------
// Scratch (__device__ globals; allocation is forbidden)
// ---------------------------------------------------------------------------
__device__ __nv_bfloat16 g_Ahi[(size_t)MM * KK];
__device__ __nv_bfloat16 g_Alo[(size_t)MM * KK];
__device__ __nv_bfloat16 g_WhiK[(size_t)NN * KK];   // transposed: [n][k]
__device__ __nv_bfloat16 g_WloK[(size_t)NN * KK];
__device__ __nv_bfloat16 g_WhiV[(size_t)NN * KK];
__device__ __nv_bfloat16 g_WloV[(size_t)NN * KK];
__device__ float g_V1[(size_t)MM * NN];
__device__ float g_dot[(size_t)MM * NH];
__device__ int   g_fm[(size_t)MM * NH * RR];
__device__ int   g_bm[(size_t)MM * NH * RR];

// ---------------------------------------------------------------------------
// Baseline-PTX helpers (sm_80+: mma.sync / ldmatrix / cp.async — NO tcgen05)
// ---------------------------------------------------------------------------
__device__ __forceinline__ uint32_t smem_u32(const void* p) {
    uint32_t a;
    asm("{ .reg .u64 t; cvta.to.shared.u64 t, %1; cvt.u32.u64 %0, t; }"
        : "=r"(a) : "l"(p));
    return a;
}

__device__ __forceinline__ void cp16(uint32_t dst, const void* src) {
    asm volatile("cp.async.cg.shared.global [%0], [%1], 16;"
                 :: "r"(dst), "l"(src));
}
__device__ __forceinline__ void cp_commit() {
    asm volatile("cp.async.commit_group;");
}
template<int N> __device__ __forceinline__ void cp_wait() {
    asm volatile("cp.async.wait_group %0;" :: "n"(N));
}

__device__ __forceinline__ void ldsm4(uint32_t* r, uint32_t addr) {
    asm volatile("ldmatrix.sync.aligned.m8n8.x4.shared.b16 {%0,%1,%2,%3}, [%4];"
                 : "=r"(r[0]), "=r"(r[1]), "=r"(r[2]), "=r"(r[3]) : "r"(addr));
}

__device__ __forceinline__ void mma16816(float* c, const uint32_t* a,
                                         uint32_t b0, uint32_t b1) {
    asm volatile(
        "mma.sync.aligned.m16n8k16.row.col.f32.bf16.bf16.f32 "
        "{%0,%1,%2,%3}, {%4,%5,%6,%7}, {%8,%9}, {%0,%1,%2,%3};"
        : "+f"(c[0]), "+f"(c[1]), "+f"(c[2]), "+f"(c[3])
        : "r"(a[0]), "r"(a[1]), "r"(a[2]), "r"(a[3]), "r"(b0), "r"(b1));
}

// ---------------------------------------------------------------------------
// Split-conversion kernels (fp32 -> bf16 hi + bf16 lo)
// ---------------------------------------------------------------------------
__device__ __forceinline__ uint32_t pack_bf2(__nv_bfloat16 a, __nv_bfloat16 b) {
    return ((uint32_t)__bfloat16_as_ushort(b) << 16) | (uint32_t)__bfloat16_as_ushort(a);
}

__global__ __launch_bounds__(256) void convA_kernel(const float* __restrict__ A) {
    size_t i = ((size_t)blockIdx.x * 256 + threadIdx.x) * 4;
    float4 v = *(const float4*)(A + i);
    __nv_bfloat16 h0 = __float2bfloat16(v.x), h1 = __float2bfloat16(v.y);
    __nv_bfloat16 h2 = __float2bfloat16(v.z), h3 = __float2bfloat16(v.w);
    __nv_bfloat16 l0 = __float2bfloat16(v.x - __bfloat162float(h0));
    __nv_bfloat16 l1 = __float2bfloat16(v.y - __bfloat162float(h1));
    __nv_bfloat16 l2 = __float2bfloat16(v.z - __bfloat162float(h2));
    __nv_bfloat16 l3 = __float2bfloat16(v.w - __bfloat162float(h3));
    uint2 ph = make_uint2(pack_bf2(h0, h1), pack_bf2(h2, h3));
    uint2 pl = make_uint2(pack_bf2(l0, l1), pack_bf2(l2, l3));
    *(uint2*)((char*)g_Ahi + i * 2) = ph;
    *(uint2*)((char*)g_Alo + i * 2) = pl;
}

// Transpose W [k][n] -> [n][k], split hi/lo. WHICH==0 -> K weights, 1 -> V.
template<int WHICH>
__global__ void convW_kernel(const float* __restrict__ W) {
    __shared__ float t[32][33];
    int bx = blockIdx.x * 32;  // n tile
    int by = blockIdx.y * 32;  // k tile
    int tx = threadIdx.x, ty = threadIdx.y;
#pragma unroll
    for (int j = 0; j < 4; j++) {
        int r = ty + j * 8;
        t[r][tx] = W[(size_t)(by + r) * NN + bx + tx];
    }
    __syncthreads();
#pragma unroll
    for (int j = 0; j < 4; j++) {
        int r = ty + j * 8;
        float x = t[tx][r];  // = W[by+tx][bx+r]
        __nv_bfloat16 h = __float2bfloat16(x);
        __nv_bfloat16 l = __float2bfloat16(x - __bfloat162float(h));
        size_t o = (size_t)(bx + r) * KK + by + tx;
        if (WHICH == 0) { g_WhiK[o] = h; g_WloK[o] = l; }
        else            { g_WhiV[o] = h; g_WloV[o] = l; }
    }
}

// ---------------------------------------------------------------------------
// mma.sync GEMM, bf16x3: C = relu(A @ Wt + bias); Wt stored [n][k].
// BM=128, BN=64 (== HD, blockIdx.x == head), BK=32, 8 warps (4x2),
// each warp 32x32. Double-buffered cp.async. Pass-major MMA ordering so
// consecutive HMMAs never share an accumulator (dep distance 8).
// __launch_bounds__(256,3): cap regs for 3 CTAs/SM.
// ---------------------------------------------------------------------------
#define A_STRIDE 80
#define OFF_AH 0
#define OFF_AL 10240
#define OFF_BH 20480
#define OFF_BL 25600
#define STAGE  30720
#define SM_TOTAL (2 * STAGE)
#define NCHUNK (KK / 32)

template<bool DOT>
__global__ __launch_bounds__(256, 3) void mma_gemm_kernel(
    const float* __restrict__ bias, const float* __restrict__ RH)
{
    extern __shared__ char smem[];
    __shared__ float sdot[128];
    const uint32_t sb = smem_u32(smem);

    const __nv_bfloat16* __restrict__ Bh = DOT ? g_WhiK : g_WhiV;
    const __nv_bfloat16* __restrict__ Bl = DOT ? g_WloK : g_WloV;

    const int tid = threadIdx.x;
    const int lane = tid & 31;
    const int wid = tid >> 5;
    const int mw = wid & 3;   // m warp row (32 rows)
    const int nw = wid >> 2;  // n warp col (32 cols)

    const int head = blockIdx.x;       // BN == HD == 64
    const int n0 = head * 64;
    const int m0 = blockIdx.y * 128;

    // ldmatrix per-lane invariant offsets
    const uint32_t a_lo = (uint32_t)((mw * 32 + (lane & 15)) * A_STRIDE
                                     + ((lane >> 4) * 8) * 2);
    const uint32_t b_lo = (uint32_t)((nw * 32 + (lane & 7) + ((lane >> 4) << 3)) * A_STRIDE
                                     + (((lane >> 3) & 1) * 8) * 2);

    // cp.async per-thread assignments
    const int a_row0 = tid >> 2;
    const int a_cc = tid & 3;

    float acc[2][4][4];
#pragma unroll
    for (int i = 0; i < 2; i++)
#pragma unroll
        for (int j = 0; j < 4; j++)
#pragma unroll
            for (int q = 0; q < 4; q++) acc[i][j][q] = 0.f;

    auto load_chunk = [&](int c, int st) {
        const int kt = c * 32;
        const uint32_t stb = sb + st * STAGE;
#pragma unroll
        for (int i = 0; i < 2; i++) {
            int row = a_row0 + i * 64;
            uint32_t so = row * A_STRIDE + a_cc * 16;
            size_t go = (size_t)(m0 + row) * KK + kt + a_cc * 8;
            cp16(stb + OFF_AH + so, g_Ahi + go);
            cp16(stb + OFF_AL + so, g_Alo + go);
        }
        {
            uint32_t so = a_row0 * A_STRIDE + a_cc * 16;
            size_t go = (size_t)(n0 + a_row0) * KK + kt + a_cc * 8;
            cp16(stb + OFF_BH + so, Bh + go);
            cp16(stb + OFF_BL + so, Bl + go);
        }
        cp_commit();
    };

    load_chunk(0, 0);

    for (int c = 0; c < NCHUNK; c++) {
        if (c + 1 < NCHUNK) {
            load_chunk(c + 1, (c + 1) & 1);
            cp_wait<1>();
        } else {
            cp_wait<0>();
        }
        __syncthreads();

        const uint32_t stb = sb + (c & 1) * STAGE;
#pragma unroll
        for (int ks = 0; ks < 2; ks++) {
            uint32_t ah[2][4], al[2][4], bh[2][4], bl[2][4];
#pragma unroll
            for (int mi = 0; mi < 2; mi++) {
                uint32_t ao = a_lo + ks * 32 + mi * (16 * A_STRIDE);
                ldsm4(ah[mi], stb + OFF_AH + ao);
                ldsm4(al[mi], stb + OFF_AL + ao);
            }
#pragma unroll
            for (int nt = 0; nt < 2; nt++) {
                uint32_t bo = b_lo + ks * 32 + nt * (16 * A_STRIDE);
                ldsm4(bh[nt], stb + OFF_BH + bo);
                ldsm4(bl[nt], stb + OFF_BL + bo);
            }
            // Pass-major: 8 independent HMMAs per pass (no acc chains)
#pragma unroll
            for (int mi = 0; mi < 2; mi++)
#pragma unroll
                for (int nj = 0; nj < 4; nj++) {
                    const int nt = nj >> 1, rb = (nj & 1) * 2;
                    mma16816(acc[mi][nj], ah[mi], bh[nt][rb], bh[nt][rb + 1]);
                }
#pragma unroll
            for (int mi = 0; mi < 2; mi++)
#pragma unroll
                for (int nj = 0; nj < 4; nj++) {
                    const int nt = nj >> 1, rb = (nj & 1) * 2;
                    mma16816(acc[mi][nj], al[mi], bh[nt][rb], bh[nt][rb + 1]);
                }
#pragma unroll
            for (int mi = 0; mi < 2; mi++)
#pragma unroll
                for (int nj = 0; nj < 4; nj++) {
                    const int nt = nj >> 1, rb = (nj & 1) * 2;
                    mma16816(acc[mi][nj], ah[mi], bl[nt][rb], bl[nt][rb + 1]);
                }
        }
        __syncthreads();
    }

    // ---- epilogue ----
    const int rrow = lane >> 2;
    const int cq = (lane & 3) * 2;

    if (!DOT) {
#pragma unroll
        for (int mi = 0; mi < 2; mi++) {
            const int r0 = m0 + mw * 32 + mi * 16 + rrow;
#pragma unroll
            for (int nj = 0; nj < 4; nj++) {
                const int n = n0 + nw * 32 + nj * 8 + cq;
                const float b0v = bias[n], b1v = bias[n + 1];
                float2 v0, v1;
                v0.x = fmaxf(acc[mi][nj][0] + b0v, 0.f);
                v0.y = fmaxf(acc[mi][nj][1] + b1v, 0.f);
                v1.x = fmaxf(acc[mi][nj][2] + b0v, 0.f);
                v1.y = fmaxf(acc[mi][nj][3] + b1v, 0.f);
                *(float2*)&g_V1[(size_t)r0 * NN + n] = v0;
                *(float2*)&g_V1[(size_t)(r0 + 8) * NN + n] = v1;
            }
        }
    } else {
        if (tid < 128) sdot[tid] = 0.f;
        __syncthreads();
#pragma unroll
        for (int mi = 0; mi < 2; mi++) {
            float s0 = 0.f, s1 = 0.f;
#pragma unroll
            for (int nj = 0; nj < 4; nj++) {
                const int n = n0 + nw * 32 + nj * 8 + cq;
                const float b0v = bias[n], b1v = bias[n + 1];
                const float rh0 = RH[n], rh1 = RH[n + 1];
                s0 += fmaxf(acc[mi][nj][0] + b0v, 0.f) * rh0
                    + fmaxf(acc[mi][nj][1] + b1v, 0.f) * rh1;
                s1 += fmaxf(acc[mi][nj][2] + b0v, 0.f) * rh0
                    + fmaxf(acc[mi][nj][3] + b1v, 0.f) * rh1;
            }
            s0 += __shfl_xor_sync(0xffffffffu, s0, 1);
            s0 += __shfl_xor_sync(0xffffffffu, s0, 2);
            s1 += __shfl_xor_sync(0xffffffffu, s1, 1);
            s1 += __shfl_xor_sync(0xffffffffu, s1, 2);
            if ((lane & 3) == 0) {
                atomicAdd(&sdot[mw * 32 + mi * 16 + rrow], s0);
                atomicAdd(&sdot[mw * 32 + mi * 16 + rrow + 8], s1);
            }
        }
        __syncthreads();
        if (tid < 128)
            g_dot[(size_t)(m0 + tid) * NH + head] = sdot[tid];
    }
}

// ---------------------------------------------------------------------------
// Scan kernel (per (b,h)): prefix-count + event list -> fm/bm index tables
// ---------------------------------------------------------------------------
__global__ __launch_bounds__(256) void scan_kernel()
{
    const int bh = blockIdx.x;
    const int b = bh / NH, h = bh % NH;

    __shared__ int s_cnt[LEN];
    __shared__ int s_e[LEN];
    __shared__ int s_wsum[8];

    const int tid = threadIdx.x;
    const int base = tid * 8;

    int c[8];
    unsigned mbits = 0;
    int run = 0;
#pragma unroll
    for (int q = 0; q < 8; q++) {
        int l = base + q;
        bool m = (l >= 1) && (g_dot[(size_t)(b * LEN + l) * NH + h] > 0.5f);
        if (m) { mbits |= 1u << q; run++; }
        c[q] = run;
    }

    const int lane = tid & 31, wd = tid >> 5;
    int v = run;
#pragma unroll
    for (int o = 1; o < 32; o <<= 1) {
        int nv = __shfl_up_sync(0xffffffffu, v, o);
        if (lane >= o) v += nv;
    }
    if (lane == 31) s_wsum[wd] = v;
    __syncthreads();
    int wpre = 0;
    for (int w = 0; w < wd; w++) wpre += s_wsum[w];
    const int excl = wpre + v - run;

#pragma unroll
    for (int q = 0; q < 8; q++) {
        s_cnt[base + q] = excl + c[q];
        if (mbits & (1u << q)) s_e[excl + c[q] - 1] = base + q;
    }
    __syncthreads();

    const int E = s_cnt[LEN - 1];

    for (int l = tid; l < LEN; l += 256) {
        int cl = s_cnt[l];
        int cp = (l > 0) ? s_cnt[l - 1] : 0;
        int fo[RR], bo[RR];
#pragma unroll
        for (int r = 0; r < RR; r++) {
            fo[r] = (cl > r) ? s_e[cl - 1 - r] : 0;
            bo[r] = (l > 0 && cp + r < E) ? s_e[cp + r] : 0;
        }
        size_t off = ((size_t)(b * LEN + l) * NH + h) * RR;
#pragma unroll
        for (int r4 = 0; r4 < RR; r4 += 4) {
            *(int4*)&g_fm[off + r4] = make_int4(fo[r4], fo[r4+1], fo[r4+2], fo[r4+3]);
            *(int4*)&g_bm[off + r4] = make_int4(bo[r4], bo[r4+1], bo[r4+2], bo[r4+3]);
        }
    }
}

// ---------------------------------------------------------------------------
// Gather + weighted sum: 16 threads per (b,l,h) tuple, float4 gathers.
// ---------------------------------------------------------------------------
__global__ __launch_bounds__(256) void gather_kernel(
    const float* __restrict__ w, float* __restrict__ out)
{
    const int t = blockIdx.x * 16 + (threadIdx.x >> 4);  // row*NH + h
    const int d4 = (threadIdx.x & 15) * 4;
    const int h = t % NH;
    const int row = t / NH;
    const int b = row >> 11;

    const int* fp = g_fm + (size_t)t * RR;
    const int* bp = g_bm + (size_t)t * RR;
    const float* wf = w + h * 2 * RR;

    const float* vb = g_V1 + (size_t)b * LEN * NN + h * HD + d4;

    float ax = 0.f, ay = 0.f, az = 0.f, aw = 0.f;
#pragma unroll
    for (int r = 0; r < RR; r++) {
        int i1 = __ldg(fp + r);
        int i2 = __ldg(bp + r);
        float w1 = __ldg(wf + r);
        float w2 = __ldg(wf + RR + r);
        float4 v1 = *(const float4*)(vb + (size_t)i1 * NN);
        float4 v2 = *(const float4*)(vb + (size_t)i2 * NN);
        ax = fmaf(w1, v1.x, fmaf(w2, v2.x, ax));
        ay = fmaf(w1, v1.y, fmaf(w2, v2.y, ay));
        az = fmaf(w1, v1.z, fmaf(w2, v2.z, az));
        aw = fmaf(w1, v1.w, fmaf(w2, v2.w, aw));
    }
    *(float4*)(out + (size_t)t * HD + d4) = make_float4(ax, ay, az, aw);
}

// ---------------------------------------------------------------------------
extern "C" void kernel_launch(void* const* d_in, const int* in_sizes, int n_in,
                              void* d_out, int out_size)
{
    const float* hidden = (const float*)d_in[0];
    const float* K1w    = (const float*)d_in[1];
    const float* K1b    = (const float*)d_in[2];
    const float* V1w    = (const float*)d_in[3];
    const float* V1b    = (const float*)d_in[4];
    const float* RH     = (const float*)d_in[5];
    const float* bw     = (const float*)d_in[6];
    float* out = (float*)d_out;

    cudaFuncSetAttribute(mma_gemm_kernel<false>,
                         cudaFuncAttributeMaxDynamicSharedMemorySize, SM_TOTAL);
    cudaFuncSetAttribute(mma_gemm_kernel<true>,
                         cudaFuncAttributeMaxDynamicSharedMemorySize, SM_TOTAL);

    // 1) Split fp32 -> bf16 hi/lo (weights also transposed to [n][k])
    convA_kernel<<<(MM * KK) / 1024, 256>>>(hidden);
    {
        dim3 tg(NN / 32, KK / 32), tb(32, 8);
        convW_kernel<0><<<tg, tb>>>(K1w);
        convW_kernel<1><<<tg, tb>>>(V1w);
    }

    // 2) Tensor-core GEMMs (bf16x3 via mma.sync)
    {
        dim3 gg(NN / 64, MM / 128);  // (12, 64)
        mma_gemm_kernel<false><<<gg, 256, SM_TOTAL>>>(V1b, nullptr);
        mma_gemm_kernel<true ><<<gg, 256, SM_TOTAL>>>(K1b, RH);
    }

    // 3) Mask scan -> index tables
    scan_kernel<<<BSZ * NH, 256>>>();

    // 4) Gather + weighted sum
    gather_kernel<<<(MM * NH) / 16, 256>>>(bw, out);
}

// round 5
// speedup vs baseline: 4.2989x; 1.2031x over previous
#include <cuda_runtime.h>
#include <cuda_bf16.h>
#include <cstdint>

// Problem constants
#define BSZ 4
#define LEN 2048
#define NH  12
#define HD  64
#define RR  16
#define HID 768
#define MM  (BSZ*LEN)   // 8192
#define NN  (NH*HD)     // 768
#define KK  HID         // 768

// ---------------------------------------------------------------------------
// Scratch (__device__ globals; allocation is forbidden)
// ---------------------------------------------------------------------------
__device__ __nv_bfloat16 g_Ahi[(size_t)MM * KK];
__device__ __nv_bfloat16 g_Alo[(size_t)MM * KK];
__device__ __nv_bfloat16 g_WhiK[(size_t)NN * KK];   // transposed: [n][k]
__device__ __nv_bfloat16 g_WloK[(size_t)NN * KK];
__device__ __nv_bfloat16 g_WhiV[(size_t)NN * KK];
__device__ __nv_bfloat16 g_WloV[(size_t)NN * KK];
__device__ float g_V1[(size_t)MM * NN];
__device__ float g_dot[(size_t)MM * NH];
__device__ int   g_fm[(size_t)MM * NH * RR];
__device__ int   g_bm[(size_t)MM * NH * RR];

// ---------------------------------------------------------------------------
// Baseline-PTX helpers (sm_80+: mma.sync / ldmatrix / cp.async — NO tcgen05)
// ---------------------------------------------------------------------------
__device__ __forceinline__ uint32_t smem_u32(const void* p) {
    uint32_t a;
    asm("{ .reg .u64 t; cvta.to.shared.u64 t, %1; cvt.u32.u64 %0, t; }"
        : "=r"(a) : "l"(p));
    return a;
}

__device__ __forceinline__ void cp16(uint32_t dst, const void* src) {
    asm volatile("cp.async.cg.shared.global [%0], [%1], 16;"
                 :: "r"(dst), "l"(src));
}
__device__ __forceinline__ void cp_commit() {
    asm volatile("cp.async.commit_group;");
}
template<int N> __device__ __forceinline__ void cp_wait() {
    asm volatile("cp.async.wait_group %0;" :: "n"(N));
}

__device__ __forceinline__ void ldsm4(uint32_t* r, uint32_t addr) {
    asm volatile("ldmatrix.sync.aligned.m8n8.x4.shared.b16 {%0,%1,%2,%3}, [%4];"
                 : "=r"(r[0]), "=r"(r[1]), "=r"(r[2]), "=r"(r[3]) : "r"(addr));
}

__device__ __forceinline__ void mma16816(float* c, const uint32_t* a,
                                         uint32_t b0, uint32_t b1) {
    asm volatile(
        "mma.sync.aligned.m16n8k16.row.col.f32.bf16.bf16.f32 "
        "{%0,%1,%2,%3}, {%4,%5,%6,%7}, {%8,%9}, {%0,%1,%2,%3};"
        : "+f"(c[0]), "+f"(c[1]), "+f"(c[2]), "+f"(c[3])
        : "r"(a[0]), "r"(a[1]), "r"(a[2]), "r"(a[3]), "r"(b0), "r"(b1));
}

// XOR-swizzled smem address: 128B rows, 16B segments, seg ^= (row & 7)
__device__ __forceinline__ uint32_t swz(int row, int seg) {
    return (uint32_t)(row * 128 + (((seg) ^ (row & 7)) << 4));
}

// ---------------------------------------------------------------------------
// Split-conversion kernels (fp32 -> bf16 hi + bf16 lo)
// ---------------------------------------------------------------------------
__device__ __forceinline__ uint32_t pack_bf2(__nv_bfloat16 a, __nv_bfloat16 b) {
    return ((uint32_t)__bfloat16_as_ushort(b) << 16) | (uint32_t)__bfloat16_as_ushort(a);
}

__global__ __launch_bounds__(256) void convA_kernel(const float* __restrict__ A) {
    size_t i = ((size_t)blockIdx.x * 256 + threadIdx.x) * 4;
    float4 v = *(const float4*)(A + i);
    __nv_bfloat16 h0 = __float2bfloat16(v.x), h1 = __float2bfloat16(v.y);
    __nv_bfloat16 h2 = __float2bfloat16(v.z), h3 = __float2bfloat16(v.w);
    __nv_bfloat16 l0 = __float2bfloat16(v.x - __bfloat162float(h0));
    __nv_bfloat16 l1 = __float2bfloat16(v.y - __bfloat162float(h1));
    __nv_bfloat16 l2 = __float2bfloat16(v.z - __bfloat162float(h2));
    __nv_bfloat16 l3 = __float2bfloat16(v.w - __bfloat162float(h3));
    uint2 ph = make_uint2(pack_bf2(h0, h1), pack_bf2(h2, h3));
    uint2 pl = make_uint2(pack_bf2(l0, l1), pack_bf2(l2, l3));
    *(uint2*)((char*)g_Ahi + i * 2) = ph;
    *(uint2*)((char*)g_Alo + i * 2) = pl;
}

// Transpose W [k][n] -> [n][k], split hi/lo. WHICH==0 -> K weights, 1 -> V.
template<int WHICH>
__global__ void convW_kernel(const float* __restrict__ W) {
    __shared__ float t[32][33];
    int bx = blockIdx.x * 32;  // n tile
    int by = blockIdx.y * 32;  // k tile
    int tx = threadIdx.x, ty = threadIdx.y;
#pragma unroll
    for (int j = 0; j < 4; j++) {
        int r = ty + j * 8;
        t[r][tx] = W[(size_t)(by + r) * NN + bx + tx];
    }
    __syncthreads();
#pragma unroll
    for (int j = 0; j < 4; j++) {
        int r = ty + j * 8;
        float x = t[tx][r];  // = W[by+tx][bx+r]
        __nv_bfloat16 h = __float2bfloat16(x);
        __nv_bfloat16 l = __float2bfloat16(x - __bfloat162float(h));
        size_t o = (size_t)(bx + r) * KK + by + tx;
        if (WHICH == 0) { g_WhiK[o] = h; g_WloK[o] = l; }
        else            { g_WhiV[o] = h; g_WloV[o] = l; }
    }
}

// ---------------------------------------------------------------------------
// FUSED mma.sync GEMM, bf16x3: per CTA computes BOTH
//   K1 = relu(A @ WtK + K1b) -> per-row dot with RH -> g_dot
//   V1 = relu(A @ WtV + V1b) -> g_V1
// BM=128, BN=128 (cols 0-63 = K head, 64-127 = V head), BK=64.
// 512 threads = 16 warps (4m x 4n), warp tile 32x32.
// 3-stage cp.async pipeline, one __syncthreads per chunk.
// SMEM per stage: Ah[128][64], Al, Bh[128][64], Bl  (XOR-swizzled 128B rows)
// ---------------------------------------------------------------------------
#define OFF_AH 0
#define OFF_AL 16384
#define OFF_BH 32768
#define OFF_BL 49152
#define STAGE  65536
#define NSTAGE 3
#define SM_TOTAL (NSTAGE * STAGE)
#define NCHUNK (KK / 64)

__global__ __launch_bounds__(512, 1) void fused_gemm_kernel(
    const float* __restrict__ Kb, const float* __restrict__ Vb,
    const float* __restrict__ RH)
{
    extern __shared__ char smem[];
    __shared__ float sdot[128];
    const uint32_t sb = smem_u32(smem);

    const int tid = threadIdx.x;
    const int lane = tid & 31;
    const int wid = tid >> 5;
    const int mw = wid & 3;   // m warp row (32 rows)
    const int nw = wid >> 2;  // n warp col (0-1: K head, 2-3: V head)

    const int head = blockIdx.x;
    const int n0 = head * 64;
    const int m0 = blockIdx.y * 128;

    // cp.async assignments: 1024 (row,seg) positions per buffer, 2 per thread
    const int p0 = tid;        // row=p>>3, seg=p&7

    float acc[2][4][4];
#pragma unroll
    for (int i = 0; i < 2; i++)
#pragma unroll
        for (int j = 0; j < 4; j++)
#pragma unroll
            for (int q = 0; q < 4; q++) acc[i][j][q] = 0.f;

    auto load_chunk = [&](int c) {
        if (c < NCHUNK) {
            const int kt = c * 64;
            const uint32_t stb = sb + (c % NSTAGE) * STAGE;
#pragma unroll
            for (int i = 0; i < 2; i++) {
                int p = p0 + i * 512;
                int row = p >> 3, seg = p & 7;
                uint32_t so = swz(row, seg);
                size_t ga = (size_t)(m0 + row) * KK + kt + seg * 8;
                cp16(stb + OFF_AH + so, g_Ahi + ga);
                cp16(stb + OFF_AL + so, g_Alo + ga);
                const __nv_bfloat16* bh;
                const __nv_bfloat16* bl;
                int grow;
                if (row < 64) { bh = g_WhiK; bl = g_WloK; grow = n0 + row; }
                else          { bh = g_WhiV; bl = g_WloV; grow = n0 + row - 64; }
                size_t gb = (size_t)grow * KK + kt + seg * 8;
                cp16(stb + OFF_BH + so, bh + gb);
                cp16(stb + OFF_BL + so, bl + gb);
            }
        }
        cp_commit();
    };

    load_chunk(0);
    load_chunk(1);

    for (int c = 0; c < NCHUNK; c++) {
        cp_wait<1>();
        __syncthreads();            // stage c visible; stage (c+2)%3 free
        load_chunk(c + 2);

        const uint32_t stb = sb + (c % NSTAGE) * STAGE;
#pragma unroll
        for (int ks = 0; ks < 4; ks++) {
            uint32_t ah[2][4], al[2][4], bh[2][4], bl[2][4];
#pragma unroll
            for (int mi = 0; mi < 2; mi++) {
                int row = mw * 32 + mi * 16 + (lane & 15);
                int seg = ks * 2 + (lane >> 4);
                uint32_t ao = swz(row, seg);
                ldsm4(ah[mi], stb + OFF_AH + ao);
                ldsm4(al[mi], stb + OFF_AL + ao);
            }
#pragma unroll
            for (int nt = 0; nt < 2; nt++) {
                int row = nw * 32 + nt * 16 + (lane & 7) + ((lane >> 4) << 3);
                int seg = ks * 2 + ((lane >> 3) & 1);
                uint32_t bo = swz(row, seg);
                ldsm4(bh[nt], stb + OFF_BH + bo);
                ldsm4(bl[nt], stb + OFF_BL + bo);
            }
            // Pass-major: 8 independent HMMAs per pass
#pragma unroll
            for (int mi = 0; mi < 2; mi++)
#pragma unroll
                for (int nj = 0; nj < 4; nj++) {
                    const int nt = nj >> 1, rb = (nj & 1) * 2;
                    mma16816(acc[mi][nj], ah[mi], bh[nt][rb], bh[nt][rb + 1]);
                }
#pragma unroll
            for (int mi = 0; mi < 2; mi++)
#pragma unroll
                for (int nj = 0; nj < 4; nj++) {
                    const int nt = nj >> 1, rb = (nj & 1) * 2;
                    mma16816(acc[mi][nj], al[mi], bh[nt][rb], bh[nt][rb + 1]);
                }
#pragma unroll
            for (int mi = 0; mi < 2; mi++)
#pragma unroll
                for (int nj = 0; nj < 4; nj++) {
                    const int nt = nj >> 1, rb = (nj & 1) * 2;
                    mma16816(acc[mi][nj], ah[mi], bl[nt][rb], bl[nt][rb + 1]);
                }
        }
        __syncthreads();
    }

    // ---- epilogue ----
    const int rrow = lane >> 2;
    const int cq = (lane & 3) * 2;

    if (tid < 128) sdot[tid] = 0.f;
    __syncthreads();

    if (nw < 2) {
        // K path: dot(relu(K1 + Kb), RH) per row
#pragma unroll
        for (int mi = 0; mi < 2; mi++) {
            float s0 = 0.f, s1 = 0.f;
#pragma unroll
            for (int nj = 0; nj < 4; nj++) {
                const int n = n0 + nw * 32 + nj * 8 + cq;
                const float b0v = Kb[n], b1v = Kb[n + 1];
                const float rh0 = RH[n], rh1 = RH[n + 1];
                s0 += fmaxf(acc[mi][nj][0] + b0v, 0.f) * rh0
                    + fmaxf(acc[mi][nj][1] + b1v, 0.f) * rh1;
                s1 += fmaxf(acc[mi][nj][2] + b0v, 0.f) * rh0
                    + fmaxf(acc[mi][nj][3] + b1v, 0.f) * rh1;
            }
            s0 += __shfl_xor_sync(0xffffffffu, s0, 1);
            s0 += __shfl_xor_sync(0xffffffffu, s0, 2);
            s1 += __shfl_xor_sync(0xffffffffu, s1, 1);
            s1 += __shfl_xor_sync(0xffffffffu, s1, 2);
            if ((lane & 3) == 0) {
                atomicAdd(&sdot[mw * 32 + mi * 16 + rrow], s0);
                atomicAdd(&sdot[mw * 32 + mi * 16 + rrow + 8], s1);
            }
        }
    } else {
        // V path: store relu(V1 + Vb)
#pragma unroll
        for (int mi = 0; mi < 2; mi++) {
            const int r0 = m0 + mw * 32 + mi * 16 + rrow;
#pragma unroll
            for (int nj = 0; nj < 4; nj++) {
                const int n = n0 + (nw - 2) * 32 + nj * 8 + cq;
                const float b0v = Vb[n], b1v = Vb[n + 1];
                float2 v0, v1;
                v0.x = fmaxf(acc[mi][nj][0] + b0v, 0.f);
                v0.y = fmaxf(acc[mi][nj][1] + b1v, 0.f);
                v1.x = fmaxf(acc[mi][nj][2] + b0v, 0.f);
                v1.y = fmaxf(acc[mi][nj][3] + b1v, 0.f);
                *(float2*)&g_V1[(size_t)r0 * NN + n] = v0;
                *(float2*)&g_V1[(size_t)(r0 + 8) * NN + n] = v1;
            }
        }
    }
    __syncthreads();
    if (tid < 128)
        g_dot[(size_t)(m0 + tid) * NH + head] = sdot[tid];
}

// ---------------------------------------------------------------------------
// Scan kernel (per (b,h)): prefix-count + event list -> fm/bm index tables
// ---------------------------------------------------------------------------
__global__ __launch_bounds__(256) void scan_kernel()
{
    const int bh = blockIdx.x;
    const int b = bh / NH, h = bh % NH;

    __shared__ int s_cnt[LEN];
    __shared__ int s_e[LEN];
    __shared__ int s_wsum[8];

    const int tid = threadIdx.x;
    const int base = tid * 8;

    int c[8];
    unsigned mbits = 0;
    int run = 0;
#pragma unroll
    for (int q = 0; q < 8; q++) {
        int l = base + q;
        bool m = (l >= 1) && (g_dot[(size_t)(b * LEN + l) * NH + h] > 0.5f);
        if (m) { mbits |= 1u << q; run++; }
        c[q] = run;
    }

    const int lane = tid & 31, wd = tid >> 5;
    int v = run;
#pragma unroll
    for (int o = 1; o < 32; o <<= 1) {
        int nv = __shfl_up_sync(0xffffffffu, v, o);
        if (lane >= o) v += nv;
    }
    if (lane == 31) s_wsum[wd] = v;
    __syncthreads();
    int wpre = 0;
    for (int w = 0; w < wd; w++) wpre += s_wsum[w];
    const int excl = wpre + v - run;

#pragma unroll
    for (int q = 0; q < 8; q++) {
        s_cnt[base + q] = excl + c[q];
        if (mbits & (1u << q)) s_e[excl + c[q] - 1] = base + q;
    }
    __syncthreads();

    const int E = s_cnt[LEN - 1];

    for (int l = tid; l < LEN; l += 256) {
        int cl = s_cnt[l];
        int cp = (l > 0) ? s_cnt[l - 1] : 0;
        int fo[RR], bo[RR];
#pragma unroll
        for (int r = 0; r < RR; r++) {
            fo[r] = (cl > r) ? s_e[cl - 1 - r] : 0;
            bo[r] = (l > 0 && cp + r < E) ? s_e[cp + r] : 0;
        }
        size_t off = ((size_t)(b * LEN + l) * NH + h) * RR;
#pragma unroll
        for (int r4 = 0; r4 < RR; r4 += 4) {
            *(int4*)&g_fm[off + r4] = make_int4(fo[r4], fo[r4+1], fo[r4+2], fo[r4+3]);
            *(int4*)&g_bm[off + r4] = make_int4(bo[r4], bo[r4+1], bo[r4+2], bo[r4+3]);
        }
    }
}

// ---------------------------------------------------------------------------
// Gather + weighted sum: 16 threads per (b,l,h) tuple, float4 gathers.
// ---------------------------------------------------------------------------
__global__ __launch_bounds__(256) void gather_kernel(
    const float* __restrict__ w, float* __restrict__ out)
{
    const int t = blockIdx.x * 16 + (threadIdx.x >> 4);  // row*NH + h
    const int d4 = (threadIdx.x & 15) * 4;
    const int h = t % NH;
    const int row = t / NH;
    const int b = row >> 11;

    const int* fp = g_fm + (size_t)t * RR;
    const int* bp = g_bm + (size_t)t * RR;
    const float* wf = w + h * 2 * RR;

    const float* vb = g_V1 + (size_t)b * LEN * NN + h * HD + d4;

    float ax = 0.f, ay = 0.f, az = 0.f, aw = 0.f;
#pragma unroll
    for (int r = 0; r < RR; r++) {
        int i1 = __ldg(fp + r);
        int i2 = __ldg(bp + r);
        float w1 = __ldg(wf + r);
        float w2 = __ldg(wf + RR + r);
        float4 v1 = *(const float4*)(vb + (size_t)i1 * NN);
        float4 v2 = *(const float4*)(vb + (size_t)i2 * NN);
        ax = fmaf(w1, v1.x, fmaf(w2, v2.x, ax));
        ay = fmaf(w1, v1.y, fmaf(w2, v2.y, ay));
        az = fmaf(w1, v1.z, fmaf(w2, v2.z, az));
        aw = fmaf(w1, v1.w, fmaf(w2, v2.w, aw));
    }
    *(float4*)(out + (size_t)t * HD + d4) = make_float4(ax, ay, az, aw);
}

// ---------------------------------------------------------------------------
extern "C" void kernel_launch(void* const* d_in, const int* in_sizes, int n_in,
                              void* d_out, int out_size)
{
    const float* hidden = (const float*)d_in[0];
    const float* K1w    = (const float*)d_in[1];
    const float* K1b    = (const float*)d_in[2];
    const float* V1w    = (const float*)d_in[3];
    const float* V1b    = (const float*)d_in[4];
    const float* RH     = (const float*)d_in[5];
    const float* bw     = (const float*)d_in[6];
    float* out = (float*)d_out;

    cudaFuncSetAttribute(fused_gemm_kernel,
                         cudaFuncAttributeMaxDynamicSharedMemorySize, SM_TOTAL);

    // 1) Split fp32 -> bf16 hi/lo (weights also transposed to [n][k])
    convA_kernel<<<(MM * KK) / 1024, 256>>>(hidden);
    {
        dim3 tg(NN / 32, KK / 32), tb(32, 8);
        convW_kernel<0><<<tg, tb>>>(K1w);
        convW_kernel<1><<<tg, tb>>>(V1w);
    }

    // 2) Fused tensor-core GEMM (K + V share A tiles)
    {
        dim3 gg(NH, MM / 128);  // (12, 64)
        fused_gemm_kernel<<<gg, 512, SM_TOTAL>>>(K1b, V1b, RH);
    }

    // 3) Mask scan -> index tables
    scan_kernel<<<BSZ * NH, 256>>>();

    // 4) Gather + weighted sum
    gather_kernel<<<(MM * NH) / 16, 256>>>(bw, out);
}